// round 10
// baseline (speedup 1.0000x reference)
#include <cuda_runtime.h>
#include <cstdint>

#define ROWS 2048
using ull = unsigned long long;

// ---- static device scratch (no runtime allocation allowed) ----------------
__device__ __align__(256) float g_h[ROWS * 1280];
__device__ __align__(256) float g_actA[ROWS * 272];
__device__ __align__(256) float g_actB[ROWS * 272];
__device__ __align__(256) float g_Wp[33849600];
__device__ __align__(256) float g_part[5400000];

__device__ __forceinline__ void fma2(ull& d, ull a, ull b) {
    asm("fma.rn.f32x2 %0, %1, %2, %0;" : "+l"(d) : "l"(a), "l"(b));
}
__device__ __forceinline__ ull mul2(ull a, ull b) {
    ull d; asm("mul.rn.f32x2 %0, %1, %2;" : "=l"(d) : "l"(a), "l"(b)); return d;
}
__device__ __forceinline__ ull dup2(float f) {
    ull d; asm("mov.b64 %0, {%1, %1};" : "=l"(d) : "f"(f)); return d;
}

// act0[b][s]: s<176 -> x, s==176 -> 1, else 0 (stride 192)
__global__ void prep_kernel(const float* __restrict__ in, float* __restrict__ act) {
    int idx = blockIdx.x * blockDim.x + threadIdx.x;
    if (idx >= ROWS * 192) return;
    int b = idx / 192, s = idx - b * 192;
    act[idx] = (s < 176) ? in[(size_t)b * 192 + s] : (s == 176 ? 1.f : 0.f);
}

// h[b][j] = relu(ids[b] . l1_W[j] + l1_b[j])
__global__ void hyper_kernel(const float* __restrict__ in, const float* __restrict__ W,
                             const float* __restrict__ bias, float* __restrict__ h) {
    int idx = blockIdx.x * blockDim.x + threadIdx.x;
    if (idx >= ROWS * 1280) return;
    int b = idx / 1280, j = idx - b * 1280;
    const float* ids = in + (size_t)b * 192 + 176;
    const float* wr = W + (size_t)j * 16;
    float acc = bias[j];
#pragma unroll
    for (int k = 0; k < 16; k++) acc += ids[k] * wr[k];
    h[idx] = fmaxf(acc, 0.f);
}

// coalesced pack of the e<128, s<IN region via 32x32 transpose:
//   Wp[(e*P + s)*OUT + m] = wW[(s*OUT + m)*128 + e]
__global__ void packT_kernel(const float* __restrict__ wW, float* __restrict__ Wp,
                             int P, int OUT) {
    __shared__ float t[32][33];
    int s = blockIdx.x, m0 = blockIdx.y * 32, e0 = blockIdx.z * 32;
    int tx = threadIdx.x, ty = threadIdx.y;  // (32, 8)
#pragma unroll
    for (int k = 0; k < 4; k++) {
        int m = m0 + ty + 8 * k;
        if (m < OUT) t[ty + 8 * k][tx] = wW[((size_t)s * OUT + m) * 128 + e0 + tx];
    }
    __syncthreads();
    int m = m0 + tx;
    if (m < OUT) {
#pragma unroll
        for (int k = 0; k < 4; k++) {
            int e = e0 + ty + 8 * k;
            Wp[((size_t)e * P + s) * OUT + m] = t[tx][ty + 8 * k];
        }
    }
}

// fill e==128 plane (wb / bb / 0) and zero s>=IN rows of e<128
__global__ void pack_rest_kernel(const float* __restrict__ wb, const float* __restrict__ bb,
                                 float* __restrict__ Wp, int IN, int P, int OUT) {
    int n1 = P * OUT;
    int per = (P - IN) * OUT;
    int tot = n1 + 128 * per;
    int idx = blockIdx.x * blockDim.x + threadIdx.x;
    if (idx >= tot) return;
    if (idx < n1) {
        int s = idx / OUT, m = idx - s * OUT;
        float v = (s < IN) ? wb[s * OUT + m] : (s == IN ? bb[m] : 0.f);
        Wp[(size_t)128 * P * OUT + idx] = v;
    } else {
        int k = idx - n1;
        int e = k / per, r = k - e * per;
        int s = IN + r / OUT, m = r % OUT;
        Wp[((size_t)e * P + s) * OUT + m] = 0.f;
    }
}

// bias partial: dst[b][m] = sum_e h_ib[b,e] * bW[m*128+e]
__global__ void bm_kernel(const float* __restrict__ h, int hcol0,
                          const float* __restrict__ bW, float* __restrict__ dst, int OUT) {
    int idx = blockIdx.x * blockDim.x + threadIdx.x;
    if (idx >= ROWS * OUT) return;
    int b = idx / OUT, m = idx - b * OUT;
    const float* hr = h + (size_t)b * 1280 + hcol0;
    const float* br = bW + (size_t)m * 128;
    float acc = 0.f;
#pragma unroll 8
    for (int e = 0; e < 128; e++) acc += hr[e] * br[e];
    dst[idx] = acc;
}

// dst[b][j] (stride DSTR): j<OUT -> relu?(sum parts); j==OUT&&padOne -> 1; else 0
__global__ void reduce_kernel(const float* __restrict__ part, int nparts, int OUT,
                              float* __restrict__ dst, int DSTR, int relu, int padOne) {
    int idx = blockIdx.x * blockDim.x + threadIdx.x;
    if (idx >= ROWS * DSTR) return;
    int b = idx / DSTR, j = idx - b * DSTR;
    float v = 0.f;
    if (j < OUT) {
        for (int z = 0; z < nparts; z++) v += part[((size_t)z * ROWS + b) * OUT + j];
        if (relu) v = fmaxf(v, 0.f);
    } else if (j == OUT && padOne) v = 1.f;
    dst[idx] = v;
}

// GEMM: part[z][b][m] = sum_{e in split z} sum_s h_e[b]*x[b][s]*Wp[e][s][m]
// BM=128 rows, BN cols. Outer loop: s-chunks of 16; inner: e (gmem w prefetch).
// w stored ONCE in smem; duplicated into f32x2 lanes via register mov.
template <int BN, int TM, int TN, int THREADS, int ECHM>
__global__ void __launch_bounds__(THREADS, 2)
gemm_hyper(const float* __restrict__ act, int SA, int NCH,
           const float* __restrict__ h, int hcol0,
           const float* __restrict__ Wp, int OUT,
           float* __restrict__ part, int ECH) {
    constexpr int BM = 128, SK = 16, BMP = 132;
    constexpr int PAIRS = TM / 2, RG = BM / TM, WPT = SK * BN / THREADS;
    __shared__ float x_t[SK * BMP];
    __shared__ float h_t[ECHM * BMP];
    __shared__ float w_t[SK * BN];

    const int tid = threadIdx.x;
    const int rowbase = blockIdx.y * BM, colbase = blockIdx.x * BN;
    const int z = blockIdx.z, eb = z * ECH;
    const int ne = min(129, eb + ECH) - eb;
    const int tr = tid % RG, tc = tid / RG;
    const int r0 = tr * TM, c0 = tc * TN;

    // stage h block: h_t[ej][r]
    for (int idx = tid; idx < BM * ne; idx += THREADS) {
        int r = idx / ne, ej = idx - r * ne, e = eb + ej;
        h_t[ej * BMP + r] = (e == 128) ? 1.f
                                       : h[(size_t)(rowbase + r) * 1280 + hcol0 + e];
    }

    ull acc[PAIRS][TN];
#pragma unroll
    for (int i = 0; i < PAIRS; i++)
#pragma unroll
        for (int j = 0; j < TN; j++) acc[i][j] = 0ULL;

    float v[WPT];
    auto loadW = [&](int e, int s0) {
#pragma unroll
        for (int u = 0; u < WPT; u++) {
            int flat = u * THREADS + tid;
            int si = flat / BN, cc = flat - si * BN;
            v[u] = Wp[((size_t)e * SA + s0 + si) * OUT + colbase + cc];
        }
    };

    for (int cs = 0; cs < NCH; cs++) {
        const int s0 = cs * SK;
        __syncthreads();
        for (int idx = tid; idx < BM * 4; idx += THREADS) {
            int r = idx >> 2, q = idx & 3;
            float4 xv = *(const float4*)(act + (size_t)(rowbase + r) * SA + s0 + 4 * q);
            x_t[(4 * q + 0) * BMP + r] = xv.x;
            x_t[(4 * q + 1) * BMP + r] = xv.y;
            x_t[(4 * q + 2) * BMP + r] = xv.z;
            x_t[(4 * q + 3) * BMP + r] = xv.w;
        }
        loadW(eb, s0);
        for (int ej = 0; ej < ne; ej++) {
            __syncthreads();
#pragma unroll
            for (int u = 0; u < WPT; u++) {
                int flat = u * THREADS + tid;
                int si = flat / BN, cc = flat - si * BN;
                w_t[si * BN + cc] = v[u];
            }
            __syncthreads();
            if (ej + 1 < ne) loadW(eb + ej + 1, s0);

            ull h2[PAIRS];
#pragma unroll
            for (int q = 0; q < PAIRS / 2; q++) {
                ulonglong2 t = *(const ulonglong2*)(h_t + ej * BMP + r0 + 4 * q);
                h2[2 * q] = t.x; h2[2 * q + 1] = t.y;
            }
#pragma unroll
            for (int sk = 0; sk < SK; sk++) {
                const float* xr = x_t + sk * BMP + r0;
                ull a2[PAIRS];
#pragma unroll
                for (int q = 0; q < PAIRS / 2; q++) {
                    ulonglong2 t = *(const ulonglong2*)(xr + 4 * q);
                    a2[2 * q] = mul2(h2[2 * q], t.x);
                    a2[2 * q + 1] = mul2(h2[2 * q + 1], t.y);
                }
                const float* wr = w_t + sk * BN + c0;
                ull wd[TN];
#pragma unroll
                for (int q = 0; q < TN / 4; q++) {
                    float4 wv = *(const float4*)(wr + 4 * q);
                    wd[4 * q + 0] = dup2(wv.x);
                    wd[4 * q + 1] = dup2(wv.y);
                    wd[4 * q + 2] = dup2(wv.z);
                    wd[4 * q + 3] = dup2(wv.w);
                }
#pragma unroll
                for (int i = 0; i < PAIRS; i++)
#pragma unroll
                    for (int j = 0; j < TN; j++) fma2(acc[i][j], a2[i], wd[j]);
            }
        }
    }

#pragma unroll
    for (int i = 0; i < PAIRS; i++)
#pragma unroll
        for (int j = 0; j < TN; j++) {
            float2 f;
            asm("mov.b64 {%0, %1}, %2;" : "=f"(f.x), "=f"(f.y) : "l"(acc[i][j]));
            int r = rowbase + r0 + 2 * i, col = colbase + c0 + j;
            part[((size_t)z * ROWS + r) * OUT + col] = f.x;
            part[((size_t)z * ROWS + r + 1) * OUT + col] = f.y;
        }
}

extern "C" void kernel_launch(void* const* d_in, const int* in_sizes, int n_in,
                              void* d_out, int out_size) {
    const float* in0 = (const float*)d_in[0];
    const float* l1W = (const float*)d_in[1];
    const float* l1b = (const float*)d_in[2];

    float *hP, *aA, *aB, *wP, *pP;
    cudaGetSymbolAddress((void**)&hP, g_h);
    cudaGetSymbolAddress((void**)&aA, g_actA);
    cudaGetSymbolAddress((void**)&aB, g_actB);
    cudaGetSymbolAddress((void**)&wP, g_Wp);
    cudaGetSymbolAddress((void**)&pP, g_part);

    prep_kernel<<<(ROWS * 192 + 255) / 256, 256>>>(in0, aA);
    hyper_kernel<<<(ROWS * 1280 + 255) / 256, 256>>>(in0, l1W, l1b, hP);

    const int IN[5]    = {176, 256, 256, 256, 256};
    const int IN1P[5]  = {192, 272, 272, 272, 272};
    const int OUT[5]   = {256, 256, 256, 256, 16};
    const int iw[5]    = {0, 2, 4, 6, 8};
    const int ib[5]    = {1, 3, 5, 7, 9};
    const int reluF[5] = {1, 1, 1, 0, 1};
    const size_t Woff[5] = {0, 6340608, 15323136, 24305664, 33288192};
    float* actIn[5]  = {aA, aB, aA, aB, aA};
    float* actOut[5] = {aB, aA, aB, aA, (float*)d_out};

    for (int L = 0; L < 5; L++) {
        const int INl = IN[L], P = IN1P[L], O = OUT[L], NCH = P / 16;
        float* Wp = wP + Woff[L];
        const float* wW = (const float*)d_in[3 + 4 * L];
        const float* wb = (const float*)d_in[4 + 4 * L];
        const float* bW = (const float*)d_in[5 + 4 * L];
        const float* bb = (const float*)d_in[6 + 4 * L];

        packT_kernel<<<dim3(INl, (O + 31) / 32, 4), dim3(32, 8)>>>(wW, Wp, P, O);
        {
            int tot = P * O + 128 * (P - INl) * O;
            pack_rest_kernel<<<(tot + 255) / 256, 256>>>(wb, bb, Wp, INl, P, O);
        }

        if (L < 4) {
            // S=9 splits, ECH=15 -> grid 2x16x9 = 288 CTAs (one 2-CTA/SM wave)
            dim3 grid(O / 128, ROWS / 128, 9);
            gemm_hyper<128, 8, 8, 256, 15><<<grid, 256>>>(
                actIn[L], P, NCH, hP, iw[L] * 128, Wp, O, pP, 15);
            bm_kernel<<<(ROWS * O + 255) / 256, 256>>>(
                hP, ib[L] * 128, bW, pP + (size_t)9 * ROWS * O, O);
            reduce_kernel<<<(ROWS * 272 + 255) / 256, 256>>>(
                pP, 10, O, actOut[L], 272, reluF[L], 1);
        } else {
            // S=22 splits, ECH=6 -> grid 1x16x22 = 352 small CTAs
            dim3 grid(1, ROWS / 128, 22);
            gemm_hyper<16, 8, 4, 64, 6><<<grid, 64>>>(
                actIn[L], P, NCH, hP, iw[L] * 128, Wp, O, pP, 6);
            bm_kernel<<<(ROWS * O + 255) / 256, 256>>>(
                hP, ib[L] * 128, bW, pP + (size_t)22 * ROWS * O, O);
            reduce_kernel<<<(ROWS * 16 + 255) / 256, 256>>>(
                pP, 23, O, (float*)d_out, 16, reluF[L], 0);
        }
    }
}

// round 11
// speedup vs baseline: 1.0009x; 1.0009x over previous
#include <cuda_runtime.h>
#include <cstdint>

#define ROWS 2048
using ull = unsigned long long;

// ---- static device scratch (no runtime allocation allowed) ----------------
__device__ __align__(256) float g_h[ROWS * 1280];
__device__ __align__(256) float g_actA[ROWS * 272];
__device__ __align__(256) float g_actB[ROWS * 272];
__device__ __align__(256) float g_Wp[33849600];
__device__ __align__(256) float g_part[5400000];

__device__ __forceinline__ void fma2(ull& d, ull a, ull b) {
    asm("fma.rn.f32x2 %0, %1, %2, %0;" : "+l"(d) : "l"(a), "l"(b));
}
__device__ __forceinline__ ull mul2(ull a, ull b) {
    ull d; asm("mul.rn.f32x2 %0, %1, %2;" : "=l"(d) : "l"(a), "l"(b)); return d;
}
__device__ __forceinline__ ull dup2(float f) {
    ull d; asm("mov.b64 %0, {%1, %1};" : "=l"(d) : "f"(f)); return d;
}

// act0[b][s]: s<176 -> x, s==176 -> 1, else 0 (stride 192)
__global__ void prep_kernel(const float* __restrict__ in, float* __restrict__ act) {
    int idx = blockIdx.x * blockDim.x + threadIdx.x;
    if (idx >= ROWS * 192) return;
    int b = idx / 192, s = idx - b * 192;
    act[idx] = (s < 176) ? in[(size_t)b * 192 + s] : (s == 176 ? 1.f : 0.f);
}

// h[b][j] = relu(ids[b] . l1_W[j] + l1_b[j])
__global__ void hyper_kernel(const float* __restrict__ in, const float* __restrict__ W,
                             const float* __restrict__ bias, float* __restrict__ h) {
    int idx = blockIdx.x * blockDim.x + threadIdx.x;
    if (idx >= ROWS * 1280) return;
    int b = idx / 1280, j = idx - b * 1280;
    const float* ids = in + (size_t)b * 192 + 176;
    const float* wr = W + (size_t)j * 16;
    float acc = bias[j];
#pragma unroll
    for (int k = 0; k < 16; k++) acc += ids[k] * wr[k];
    h[idx] = fmaxf(acc, 0.f);
}

// coalesced pack of the e<128, s<IN region via 32x32 transpose:
//   Wp[(e*P + s)*OUT + m] = wW[(s*OUT + m)*128 + e]
__global__ void packT_kernel(const float* __restrict__ wW, float* __restrict__ Wp,
                             int P, int OUT) {
    __shared__ float t[32][33];
    int s = blockIdx.x, m0 = blockIdx.y * 32, e0 = blockIdx.z * 32;
    int tx = threadIdx.x, ty = threadIdx.y;  // (32, 8)
#pragma unroll
    for (int k = 0; k < 4; k++) {
        int m = m0 + ty + 8 * k;
        if (m < OUT) t[ty + 8 * k][tx] = wW[((size_t)s * OUT + m) * 128 + e0 + tx];
    }
    __syncthreads();
    int m = m0 + tx;
    if (m < OUT) {
#pragma unroll
        for (int k = 0; k < 4; k++) {
            int e = e0 + ty + 8 * k;
            Wp[((size_t)e * P + s) * OUT + m] = t[tx][ty + 8 * k];
        }
    }
}

// fill e==128 plane (wb / bb / 0) and zero s>=IN rows of e<128
__global__ void pack_rest_kernel(const float* __restrict__ wb, const float* __restrict__ bb,
                                 float* __restrict__ Wp, int IN, int P, int OUT) {
    int n1 = P * OUT;
    int per = (P - IN) * OUT;
    int tot = n1 + 128 * per;
    int idx = blockIdx.x * blockDim.x + threadIdx.x;
    if (idx >= tot) return;
    if (idx < n1) {
        int s = idx / OUT, m = idx - s * OUT;
        float v = (s < IN) ? wb[s * OUT + m] : (s == IN ? bb[m] : 0.f);
        Wp[(size_t)128 * P * OUT + idx] = v;
    } else {
        int k = idx - n1;
        int e = k / per, r = k - e * per;
        int s = IN + r / OUT, m = r % OUT;
        Wp[((size_t)e * P + s) * OUT + m] = 0.f;
    }
}

// bias partial: dst[b][m] = sum_e h_ib[b,e] * bW[m*128+e]
__global__ void bm_kernel(const float* __restrict__ h, int hcol0,
                          const float* __restrict__ bW, float* __restrict__ dst, int OUT) {
    int idx = blockIdx.x * blockDim.x + threadIdx.x;
    if (idx >= ROWS * OUT) return;
    int b = idx / OUT, m = idx - b * OUT;
    const float* hr = h + (size_t)b * 1280 + hcol0;
    const float* br = bW + (size_t)m * 128;
    float acc = 0.f;
#pragma unroll 8
    for (int e = 0; e < 128; e++) acc += hr[e] * br[e];
    dst[idx] = acc;
}

// dst[b][j] (stride DSTR): j<OUT -> relu?(sum parts); j==OUT&&padOne -> 1; else 0
__global__ void reduce_kernel(const float* __restrict__ part, int nparts, int OUT,
                              float* __restrict__ dst, int DSTR, int relu, int padOne) {
    int idx = blockIdx.x * blockDim.x + threadIdx.x;
    if (idx >= ROWS * DSTR) return;
    int b = idx / DSTR, j = idx - b * DSTR;
    float v = 0.f;
    if (j < OUT) {
        for (int z = 0; z < nparts; z++) v += part[((size_t)z * ROWS + b) * OUT + j];
        if (relu) v = fmaxf(v, 0.f);
    } else if (j == OUT && padOne) v = 1.f;
    dst[idx] = v;
}

// GEMM: part[z][b][m] = sum_{e in split z} sum_s h_e[b]*x[b][s]*Wp[e][s][m]
// BM=128 rows, BN cols. Outer loop: s-chunks of 16; inner: e (gmem w prefetch).
// w stored ONCE in smem; duplicated into f32x2 lanes via register mov.
template <int BN, int TM, int TN, int THREADS, int ECHM>
__global__ void __launch_bounds__(THREADS, 2)
gemm_hyper(const float* __restrict__ act, int SA, int NCH,
           const float* __restrict__ h, int hcol0,
           const float* __restrict__ Wp, int OUT,
           float* __restrict__ part, int ECH) {
    constexpr int BM = 128, SK = 16, BMP = 132;
    constexpr int PAIRS = TM / 2, RG = BM / TM, WPT = SK * BN / THREADS;
    __shared__ float x_t[SK * BMP];
    __shared__ float h_t[ECHM * BMP];
    __shared__ float w_t[SK * BN];

    const int tid = threadIdx.x;
    const int rowbase = blockIdx.y * BM, colbase = blockIdx.x * BN;
    const int z = blockIdx.z, eb = z * ECH;
    const int ne = min(129, eb + ECH) - eb;
    const int tr = tid % RG, tc = tid / RG;
    const int r0 = tr * TM, c0 = tc * TN;

    // stage h block: h_t[ej][r]
    for (int idx = tid; idx < BM * ne; idx += THREADS) {
        int r = idx / ne, ej = idx - r * ne, e = eb + ej;
        h_t[ej * BMP + r] = (e == 128) ? 1.f
                                       : h[(size_t)(rowbase + r) * 1280 + hcol0 + e];
    }

    ull acc[PAIRS][TN];
#pragma unroll
    for (int i = 0; i < PAIRS; i++)
#pragma unroll
        for (int j = 0; j < TN; j++) acc[i][j] = 0ULL;

    float v[WPT];
    auto loadW = [&](int e, int s0) {
#pragma unroll
        for (int u = 0; u < WPT; u++) {
            int flat = u * THREADS + tid;
            int si = flat / BN, cc = flat - si * BN;
            v[u] = Wp[((size_t)e * SA + s0 + si) * OUT + colbase + cc];
        }
    };

    for (int cs = 0; cs < NCH; cs++) {
        const int s0 = cs * SK;
        __syncthreads();
        for (int idx = tid; idx < BM * 4; idx += THREADS) {
            int r = idx >> 2, q = idx & 3;
            float4 xv = *(const float4*)(act + (size_t)(rowbase + r) * SA + s0 + 4 * q);
            x_t[(4 * q + 0) * BMP + r] = xv.x;
            x_t[(4 * q + 1) * BMP + r] = xv.y;
            x_t[(4 * q + 2) * BMP + r] = xv.z;
            x_t[(4 * q + 3) * BMP + r] = xv.w;
        }
        loadW(eb, s0);
        for (int ej = 0; ej < ne; ej++) {
            __syncthreads();
#pragma unroll
            for (int u = 0; u < WPT; u++) {
                int flat = u * THREADS + tid;
                int si = flat / BN, cc = flat - si * BN;
                w_t[si * BN + cc] = v[u];
            }
            __syncthreads();
            if (ej + 1 < ne) loadW(eb + ej + 1, s0);

            ull h2[PAIRS];
#pragma unroll
            for (int q = 0; q < PAIRS / 2; q++) {
                ulonglong2 t = *(const ulonglong2*)(h_t + ej * BMP + r0 + 4 * q);
                h2[2 * q] = t.x; h2[2 * q + 1] = t.y;
            }
#pragma unroll
            for (int sk = 0; sk < SK; sk++) {
                const float* xr = x_t + sk * BMP + r0;
                ull a2[PAIRS];
#pragma unroll
                for (int q = 0; q < PAIRS / 2; q++) {
                    ulonglong2 t = *(const ulonglong2*)(xr + 4 * q);
                    a2[2 * q] = mul2(h2[2 * q], t.x);
                    a2[2 * q + 1] = mul2(h2[2 * q + 1], t.y);
                }
                const float* wr = w_t + sk * BN + c0;
                ull wd[TN];
#pragma unroll
                for (int q = 0; q < TN / 4; q++) {
                    float4 wv = *(const float4*)(wr + 4 * q);
                    wd[4 * q + 0] = dup2(wv.x);
                    wd[4 * q + 1] = dup2(wv.y);
                    wd[4 * q + 2] = dup2(wv.z);
                    wd[4 * q + 3] = dup2(wv.w);
                }
#pragma unroll
                for (int i = 0; i < PAIRS; i++)
#pragma unroll
                    for (int j = 0; j < TN; j++) fma2(acc[i][j], a2[i], wd[j]);
            }
        }
    }

#pragma unroll
    for (int i = 0; i < PAIRS; i++)
#pragma unroll
        for (int j = 0; j < TN; j++) {
            float2 f;
            asm("mov.b64 {%0, %1}, %2;" : "=f"(f.x), "=f"(f.y) : "l"(acc[i][j]));
            int r = rowbase + r0 + 2 * i, col = colbase + c0 + j;
            part[((size_t)z * ROWS + r) * OUT + col] = f.x;
            part[((size_t)z * ROWS + r + 1) * OUT + col] = f.y;
        }
}

extern "C" void kernel_launch(void* const* d_in, const int* in_sizes, int n_in,
                              void* d_out, int out_size) {
    const float* in0 = (const float*)d_in[0];
    const float* l1W = (const float*)d_in[1];
    const float* l1b = (const float*)d_in[2];

    float *hP, *aA, *aB, *wP, *pP;
    cudaGetSymbolAddress((void**)&hP, g_h);
    cudaGetSymbolAddress((void**)&aA, g_actA);
    cudaGetSymbolAddress((void**)&aB, g_actB);
    cudaGetSymbolAddress((void**)&wP, g_Wp);
    cudaGetSymbolAddress((void**)&pP, g_part);

    prep_kernel<<<(ROWS * 192 + 255) / 256, 256>>>(in0, aA);
    hyper_kernel<<<(ROWS * 1280 + 255) / 256, 256>>>(in0, l1W, l1b, hP);

    const int IN[5]    = {176, 256, 256, 256, 256};
    const int IN1P[5]  = {192, 272, 272, 272, 272};
    const int OUT[5]   = {256, 256, 256, 256, 16};
    const int iw[5]    = {0, 2, 4, 6, 8};
    const int ib[5]    = {1, 3, 5, 7, 9};
    const int reluF[5] = {1, 1, 1, 0, 1};
    const size_t Woff[5] = {0, 6340608, 15323136, 24305664, 33288192};
    float* actIn[5]  = {aA, aB, aA, aB, aA};
    float* actOut[5] = {aB, aA, aB, aA, (float*)d_out};

    for (int L = 0; L < 5; L++) {
        const int INl = IN[L], P = IN1P[L], O = OUT[L], NCH = P / 16;
        float* Wp = wP + Woff[L];
        const float* wW = (const float*)d_in[3 + 4 * L];
        const float* wb = (const float*)d_in[4 + 4 * L];
        const float* bW = (const float*)d_in[5 + 4 * L];
        const float* bb = (const float*)d_in[6 + 4 * L];

        packT_kernel<<<dim3(INl, (O + 31) / 32, 4), dim3(32, 8)>>>(wW, Wp, P, O);
        {
            int tot = P * O + 128 * (P - INl) * O;
            pack_rest_kernel<<<(tot + 255) / 256, 256>>>(wb, bb, Wp, INl, P, O);
        }

        if (L < 4) {
            // S=9 splits, ECH=15 -> grid 2x16x9 = 288 CTAs (one 2-CTA/SM wave)
            dim3 grid(O / 128, ROWS / 128, 9);
            gemm_hyper<128, 8, 8, 256, 15><<<grid, 256>>>(
                actIn[L], P, NCH, hP, iw[L] * 128, Wp, O, pP, 15);
            bm_kernel<<<(ROWS * O + 255) / 256, 256>>>(
                hP, ib[L] * 128, bW, pP + (size_t)9 * ROWS * O, O);
            reduce_kernel<<<(ROWS * 272 + 255) / 256, 256>>>(
                pP, 10, O, actOut[L], 272, reluF[L], 1);
        } else {
            // S=22 splits, ECH=6 -> grid 1x16x22 = 352 small CTAs
            dim3 grid(1, ROWS / 128, 22);
            gemm_hyper<16, 8, 4, 64, 6><<<grid, 64>>>(
                actIn[L], P, NCH, hP, iw[L] * 128, Wp, O, pP, 6);
            bm_kernel<<<(ROWS * O + 255) / 256, 256>>>(
                hP, ib[L] * 128, bW, pP + (size_t)22 * ROWS * O, O);
            reduce_kernel<<<(ROWS * 16 + 255) / 256, 256>>>(
                pP, 23, O, (float*)d_out, 16, reluF[L], 0);
        }
    }
}

// round 12
// speedup vs baseline: 1.0068x; 1.0059x over previous
#include <cuda_runtime.h>
#include <cstdint>

#define ROWS 2048
using ull = unsigned long long;

// ---- static device scratch (no runtime allocation allowed) ----------------
__device__ __align__(256) float g_h[ROWS * 1280];
__device__ __align__(256) float g_actA[ROWS * 272];
__device__ __align__(256) float g_actB[ROWS * 272];
__device__ __align__(256) float g_Wp[33849600];
__device__ __align__(256) float g_part[5400000];

__device__ __forceinline__ void fma2(ull& d, ull a, ull b) {
    asm("fma.rn.f32x2 %0, %1, %2, %0;" : "+l"(d) : "l"(a), "l"(b));
}
__device__ __forceinline__ ull mul2(ull a, ull b) {
    ull d; asm("mul.rn.f32x2 %0, %1, %2;" : "=l"(d) : "l"(a), "l"(b)); return d;
}
__device__ __forceinline__ ull dup2(float f) {
    ull d; asm("mov.b64 %0, {%1, %1};" : "=l"(d) : "f"(f)); return d;
}

// act0[b][s]: s<176 -> x, s==176 -> 1, else 0 (stride 192)
__global__ void prep_kernel(const float* __restrict__ in, float* __restrict__ act) {
    int idx = blockIdx.x * blockDim.x + threadIdx.x;
    if (idx >= ROWS * 192) return;
    int b = idx / 192, s = idx - b * 192;
    act[idx] = (s < 176) ? in[(size_t)b * 192 + s] : (s == 176 ? 1.f : 0.f);
}

// h[b][j] = relu(ids[b] . l1_W[j] + l1_b[j])
__global__ void hyper_kernel(const float* __restrict__ in, const float* __restrict__ W,
                             const float* __restrict__ bias, float* __restrict__ h) {
    int idx = blockIdx.x * blockDim.x + threadIdx.x;
    if (idx >= ROWS * 1280) return;
    int b = idx / 1280, j = idx - b * 1280;
    const float* ids = in + (size_t)b * 192 + 176;
    const float* wr = W + (size_t)j * 16;
    float acc = bias[j];
#pragma unroll
    for (int k = 0; k < 16; k++) acc += ids[k] * wr[k];
    h[idx] = fmaxf(acc, 0.f);
}

// coalesced pack of the e<128, s<IN region via 32x32 transpose:
//   Wp[(e*P + s)*OUT + m] = wW[(s*OUT + m)*128 + e]
__global__ void packT_kernel(const float* __restrict__ wW, float* __restrict__ Wp,
                             int P, int OUT) {
    __shared__ float t[32][33];
    int s = blockIdx.x, m0 = blockIdx.y * 32, e0 = blockIdx.z * 32;
    int tx = threadIdx.x, ty = threadIdx.y;  // (32, 8)
#pragma unroll
    for (int k = 0; k < 4; k++) {
        int m = m0 + ty + 8 * k;
        if (m < OUT) t[ty + 8 * k][tx] = wW[((size_t)s * OUT + m) * 128 + e0 + tx];
    }
    __syncthreads();
    int m = m0 + tx;
    if (m < OUT) {
#pragma unroll
        for (int k = 0; k < 4; k++) {
            int e = e0 + ty + 8 * k;
            Wp[((size_t)e * P + s) * OUT + m] = t[tx][ty + 8 * k];
        }
    }
}

// fill e==128 plane (wb / bb / 0) and zero s>=IN rows of e<128
__global__ void pack_rest_kernel(const float* __restrict__ wb, const float* __restrict__ bb,
                                 float* __restrict__ Wp, int IN, int P, int OUT) {
    int n1 = P * OUT;
    int per = (P - IN) * OUT;
    int tot = n1 + 128 * per;
    int idx = blockIdx.x * blockDim.x + threadIdx.x;
    if (idx >= tot) return;
    if (idx < n1) {
        int s = idx / OUT, m = idx - s * OUT;
        float v = (s < IN) ? wb[s * OUT + m] : (s == IN ? bb[m] : 0.f);
        Wp[(size_t)128 * P * OUT + idx] = v;
    } else {
        int k = idx - n1;
        int e = k / per, r = k - e * per;
        int s = IN + r / OUT, m = r % OUT;
        Wp[((size_t)e * P + s) * OUT + m] = 0.f;
    }
}

// bias partial: dst[b][m] = sum_e h_ib[b,e] * bW[m*128+e]
__global__ void bm_kernel(const float* __restrict__ h, int hcol0,
                          const float* __restrict__ bW, float* __restrict__ dst, int OUT) {
    int idx = blockIdx.x * blockDim.x + threadIdx.x;
    if (idx >= ROWS * OUT) return;
    int b = idx / OUT, m = idx - b * OUT;
    const float* hr = h + (size_t)b * 1280 + hcol0;
    const float* br = bW + (size_t)m * 128;
    float acc = 0.f;
#pragma unroll 8
    for (int e = 0; e < 128; e++) acc += hr[e] * br[e];
    dst[idx] = acc;
}

// dst[b][j] (stride DSTR): j<OUT -> relu?(sum parts); j==OUT&&padOne -> 1; else 0
__global__ void reduce_kernel(const float* __restrict__ part, int nparts, int OUT,
                              float* __restrict__ dst, int DSTR, int relu, int padOne) {
    int idx = blockIdx.x * blockDim.x + threadIdx.x;
    if (idx >= ROWS * DSTR) return;
    int b = idx / DSTR, j = idx - b * DSTR;
    float v = 0.f;
    if (j < OUT) {
        for (int z = 0; z < nparts; z++) v += part[((size_t)z * ROWS + b) * OUT + j];
        if (relu) v = fmaxf(v, 0.f);
    } else if (j == OUT && padOne) v = 1.f;
    dst[idx] = v;
}

// GEMM: part[z][b][m] = sum_{e in split z} sum_s h_e[b]*x[b][s]*Wp[e][s][m]
// BM=128 rows, BN cols. Outer loop: s-chunks of 16; inner: e (gmem w prefetch).
// w stored ONCE in smem; duplicated into f32x2 lanes via register mov.
template <int BN, int TM, int TN, int THREADS, int ECHM>
__global__ void __launch_bounds__(THREADS, 2)
gemm_hyper(const float* __restrict__ act, int SA, int NCH,
           const float* __restrict__ h, int hcol0,
           const float* __restrict__ Wp, int OUT,
           float* __restrict__ part, int ECH) {
    constexpr int BM = 128, SK = 16, BMP = 132;
    constexpr int PAIRS = TM / 2, RG = BM / TM, WPT = SK * BN / THREADS;
    __shared__ float x_t[SK * BMP];
    __shared__ float h_t[ECHM * BMP];
    __shared__ float w_t[SK * BN];

    const int tid = threadIdx.x;
    const int rowbase = blockIdx.y * BM, colbase = blockIdx.x * BN;
    const int z = blockIdx.z, eb = z * ECH;
    const int ne = min(129, eb + ECH) - eb;
    const int tr = tid % RG, tc = tid / RG;
    const int r0 = tr * TM, c0 = tc * TN;

    // stage h block: h_t[ej][r]
    for (int idx = tid; idx < BM * ne; idx += THREADS) {
        int r = idx / ne, ej = idx - r * ne, e = eb + ej;
        h_t[ej * BMP + r] = (e == 128) ? 1.f
                                       : h[(size_t)(rowbase + r) * 1280 + hcol0 + e];
    }

    ull acc[PAIRS][TN];
#pragma unroll
    for (int i = 0; i < PAIRS; i++)
#pragma unroll
        for (int j = 0; j < TN; j++) acc[i][j] = 0ULL;

    float v[WPT];
    auto loadW = [&](int e, int s0) {
#pragma unroll
        for (int u = 0; u < WPT; u++) {
            int flat = u * THREADS + tid;
            int si = flat / BN, cc = flat - si * BN;
            v[u] = Wp[((size_t)e * SA + s0 + si) * OUT + colbase + cc];
        }
    };

    for (int cs = 0; cs < NCH; cs++) {
        const int s0 = cs * SK;
        __syncthreads();
        for (int idx = tid; idx < BM * 4; idx += THREADS) {
            int r = idx >> 2, q = idx & 3;
            float4 xv = *(const float4*)(act + (size_t)(rowbase + r) * SA + s0 + 4 * q);
            x_t[(4 * q + 0) * BMP + r] = xv.x;
            x_t[(4 * q + 1) * BMP + r] = xv.y;
            x_t[(4 * q + 2) * BMP + r] = xv.z;
            x_t[(4 * q + 3) * BMP + r] = xv.w;
        }
        loadW(eb, s0);
        for (int ej = 0; ej < ne; ej++) {
            __syncthreads();
#pragma unroll
            for (int u = 0; u < WPT; u++) {
                int flat = u * THREADS + tid;
                int si = flat / BN, cc = flat - si * BN;
                w_t[si * BN + cc] = v[u];
            }
            __syncthreads();
            if (ej + 1 < ne) loadW(eb + ej + 1, s0);

            ull h2[PAIRS];
#pragma unroll
            for (int q = 0; q < PAIRS / 2; q++) {
                ulonglong2 t = *(const ulonglong2*)(h_t + ej * BMP + r0 + 4 * q);
                h2[2 * q] = t.x; h2[2 * q + 1] = t.y;
            }
#pragma unroll
            for (int sk = 0; sk < SK; sk++) {
                const float* xr = x_t + sk * BMP + r0;
                ull a2[PAIRS];
#pragma unroll
                for (int q = 0; q < PAIRS / 2; q++) {
                    ulonglong2 t = *(const ulonglong2*)(xr + 4 * q);
                    a2[2 * q] = mul2(h2[2 * q], t.x);
                    a2[2 * q + 1] = mul2(h2[2 * q + 1], t.y);
                }
                const float* wr = w_t + sk * BN + c0;
                ull wd[TN];
#pragma unroll
                for (int q = 0; q < TN / 4; q++) {
                    float4 wv = *(const float4*)(wr + 4 * q);
                    wd[4 * q + 0] = dup2(wv.x);
                    wd[4 * q + 1] = dup2(wv.y);
                    wd[4 * q + 2] = dup2(wv.z);
                    wd[4 * q + 3] = dup2(wv.w);
                }
#pragma unroll
                for (int i = 0; i < PAIRS; i++)
#pragma unroll
                    for (int j = 0; j < TN; j++) fma2(acc[i][j], a2[i], wd[j]);
            }
        }
    }

#pragma unroll
    for (int i = 0; i < PAIRS; i++)
#pragma unroll
        for (int j = 0; j < TN; j++) {
            float2 f;
            asm("mov.b64 {%0, %1}, %2;" : "=f"(f.x), "=f"(f.y) : "l"(acc[i][j]));
            int r = rowbase + r0 + 2 * i, col = colbase + c0 + j;
            part[((size_t)z * ROWS + r) * OUT + col] = f.x;
            part[((size_t)z * ROWS + r + 1) * OUT + col] = f.y;
        }
}

extern "C" void kernel_launch(void* const* d_in, const int* in_sizes, int n_in,
                              void* d_out, int out_size) {
    const float* in0 = (const float*)d_in[0];
    const float* l1W = (const float*)d_in[1];
    const float* l1b = (const float*)d_in[2];

    float *hP, *aA, *aB, *wP, *pP;
    cudaGetSymbolAddress((void**)&hP, g_h);
    cudaGetSymbolAddress((void**)&aA, g_actA);
    cudaGetSymbolAddress((void**)&aB, g_actB);
    cudaGetSymbolAddress((void**)&wP, g_Wp);
    cudaGetSymbolAddress((void**)&pP, g_part);

    prep_kernel<<<(ROWS * 192 + 255) / 256, 256>>>(in0, aA);
    hyper_kernel<<<(ROWS * 1280 + 255) / 256, 256>>>(in0, l1W, l1b, hP);

    const int IN[5]    = {176, 256, 256, 256, 256};
    const int IN1P[5]  = {192, 272, 272, 272, 272};
    const int OUT[5]   = {256, 256, 256, 256, 16};
    const int iw[5]    = {0, 2, 4, 6, 8};
    const int ib[5]    = {1, 3, 5, 7, 9};
    const int reluF[5] = {1, 1, 1, 0, 1};
    const size_t Woff[5] = {0, 6340608, 15323136, 24305664, 33288192};
    float* actIn[5]  = {aA, aB, aA, aB, aA};
    float* actOut[5] = {aB, aA, aB, aA, (float*)d_out};

    for (int L = 0; L < 5; L++) {
        const int INl = IN[L], P = IN1P[L], O = OUT[L], NCH = P / 16;
        float* Wp = wP + Woff[L];
        const float* wW = (const float*)d_in[3 + 4 * L];
        const float* wb = (const float*)d_in[4 + 4 * L];
        const float* bW = (const float*)d_in[5 + 4 * L];
        const float* bb = (const float*)d_in[6 + 4 * L];

        packT_kernel<<<dim3(INl, (O + 31) / 32, 4), dim3(32, 8)>>>(wW, Wp, P, O);
        {
            int tot = P * O + 128 * (P - INl) * O;
            pack_rest_kernel<<<(tot + 255) / 256, 256>>>(wb, bb, Wp, INl, P, O);
        }

        if (L < 4) {
            // S=9 splits, ECH=15 -> grid 2x16x9 = 288 CTAs (one 2-CTA/SM wave)
            dim3 grid(O / 128, ROWS / 128, 9);
            gemm_hyper<128, 8, 8, 256, 15><<<grid, 256>>>(
                actIn[L], P, NCH, hP, iw[L] * 128, Wp, O, pP, 15);
            bm_kernel<<<(ROWS * O + 255) / 256, 256>>>(
                hP, ib[L] * 128, bW, pP + (size_t)9 * ROWS * O, O);
            reduce_kernel<<<(ROWS * 272 + 255) / 256, 256>>>(
                pP, 10, O, actOut[L], 272, reluF[L], 1);
        } else {
            // S=22 splits, ECH=6 -> grid 1x16x22 = 352 small CTAs
            dim3 grid(1, ROWS / 128, 22);
            gemm_hyper<16, 8, 4, 64, 6><<<grid, 64>>>(
                actIn[L], P, NCH, hP, iw[L] * 128, Wp, O, pP, 6);
            bm_kernel<<<(ROWS * O + 255) / 256, 256>>>(
                hP, ib[L] * 128, bW, pP + (size_t)22 * ROWS * O, O);
            reduce_kernel<<<(ROWS * 16 + 255) / 256, 256>>>(
                pP, 23, O, (float*)d_out, 16, reluF[L], 0);
        }
    }
}